// round 1
// baseline (speedup 1.0000x reference)
#include <cuda_runtime.h>
#include <cuda_bf16.h>
#include <stdint.h>

// Periodic radius-graph: B=4, N=512, K=27.
// Outputs concatenated in d_out (float32):
//   [0,      S)   distances   [B,N,N,K]
//   [S,     4S)   distance_vec[B,N,N,K,3]
//   [4S,    5S)   mask        [B,N,N,K]  (0.0/1.0)
//   [5S, 5S+81B)  offset_cart [B,27,3]
// with S = B*N*N*K.

#define KIMG 27
#define MAXN 512

__global__ __launch_bounds__(256)
void radius_graph_kernel(const float* __restrict__ pos,
                         const float* __restrict__ cell,
                         float* __restrict__ out,
                         int B, int N, size_t S)
{
    __shared__ float spos[MAXN * 3];
    __shared__ float soff[KIMG * 3];

    const int bi = blockIdx.x;        // 0 .. B*N-1
    const int b  = bi / N;
    const int i  = bi - b * N;

    // Load this structure's positions into shared memory (6 KB)
    const float* posb = pos + (size_t)b * N * 3;
    for (int t = threadIdx.x; t < N * 3; t += blockDim.x)
        spos[t] = posb[t];

    // Compute the 27 cartesian image offsets: off[k][d] = sum_c frac[k][c]*cell[b][c][d]
    if (threadIdx.x < KIMG * 3) {
        const int k = threadIdx.x / 3;
        const int d = threadIdx.x - k * 3;
        const int f0 = (k / 9) - 1;
        const int f1 = ((k / 3) % 3) - 1;
        const int f2 = (k % 3) - 1;
        const float* cb = cell + b * 9;
        soff[threadIdx.x] = (float)f0 * cb[0 * 3 + d]
                          + (float)f1 * cb[1 * 3 + d]
                          + (float)f2 * cb[2 * 3 + d];
    }
    __syncthreads();

    const float pix = spos[i * 3 + 0];
    const float piy = spos[i * 3 + 1];
    const float piz = spos[i * 3 + 2];

    float* __restrict__ dist_out = out;
    float* __restrict__ vec_out  = out + S;
    float* __restrict__ mask_out = out + 4 * S;

    const int    NK   = N * KIMG;
    const size_t base = (size_t)bi * (size_t)NK;

    for (int t = threadIdx.x; t < NK; t += blockDim.x) {
        const int j = t / KIMG;
        const int k = t - j * KIMG;

        // vec = (pos_j + offset_k) - pos_i  (reference association order)
        const float vx = (spos[j * 3 + 0] + soff[k * 3 + 0]) - pix;
        const float vy = (spos[j * 3 + 1] + soff[k * 3 + 1]) - piy;
        const float vz = (spos[j * 3 + 2] + soff[k * 3 + 2]) - piz;

        const float sq = vx * vx + vy * vy + vz * vz;
        const bool  m  = (sq > 1e-8f) && (sq <= 25.0f);
        const float mf = m ? 1.0f : 0.0f;
        const float dd = m ? sqrtf(sq) : 0.0f;

        const size_t idx = base + (size_t)t;
        dist_out[idx]         = dd;
        mask_out[idx]         = mf;
        vec_out[idx * 3 + 0]  = vx * mf;
        vec_out[idx * 3 + 1]  = vy * mf;
        vec_out[idx * 3 + 2]  = vz * mf;
    }

    // offset_cart tail: one block per structure (the i==0 block) writes 81 floats
    if (i == 0 && threadIdx.x < KIMG * 3) {
        out[5 * S + (size_t)b * (KIMG * 3) + threadIdx.x] = soff[threadIdx.x];
    }
}

extern "C" void kernel_launch(void* const* d_in, const int* in_sizes, int n_in,
                              void* d_out, int out_size)
{
    const float* pos  = (const float*)d_in[0];  // [B, N, 3]
    const float* cell = (const float*)d_in[1];  // [B, 3, 3]

    const int B = in_sizes[1] / 9;              // 4
    const int N = in_sizes[0] / (3 * B);        // 512
    const size_t S = (size_t)B * N * N * KIMG;  // 28,311,552

    float* out = (float*)d_out;

    dim3 grid(B * N);
    dim3 block(256);
    radius_graph_kernel<<<grid, block>>>(pos, cell, out, B, N, S);
}

// round 4
// speedup vs baseline: 1.0693x; 1.0693x over previous
#include <cuda_runtime.h>
#include <cuda_bf16.h>
#include <stdint.h>

// Periodic radius-graph: B=4, N=512, K=27.
// Outputs concatenated in d_out (float32):
//   [0,      S)   distances   [B,N,N,K]
//   [S,     4S)   distance_vec[B,N,N,K,3]
//   [4S,    5S)   mask        [B,N,N,K]  (0.0/1.0)
//   [5S, 5S+81B)  offset_cart [B,27,3]
// with S = B*N*N*K.

#define KIMG 27
#define MAXN 512
#define CH   1536          // chunk of t-elements staged per iteration (= 6*256)
#define TPB  256

__global__ __launch_bounds__(TPB)
void radius_graph_kernel(const float* __restrict__ pos,
                         const float* __restrict__ cell,
                         float* __restrict__ out,
                         int B, int N, size_t S)
{
    __shared__ float spos[MAXN * 3];
    __shared__ float soff[KIMG * 3];
    __shared__ __align__(16) float svec[CH * 3];   // 18 KB staging for vec

    const int bi = blockIdx.x;        // 0 .. B*N-1
    const int b  = bi / N;
    const int i  = bi - b * N;

    // Load this structure's positions into shared memory (6 KB)
    const float* posb = pos + (size_t)b * N * 3;
    for (int t = threadIdx.x; t < N * 3; t += TPB)
        spos[t] = posb[t];

    // 27 cartesian image offsets: off[k][d] = sum_c frac[k][c]*cell[b][c][d]
    if (threadIdx.x < KIMG * 3) {
        const int k = threadIdx.x / 3;
        const int d = threadIdx.x - k * 3;
        const int f0 = (k / 9) - 1;
        const int f1 = ((k / 3) % 3) - 1;
        const int f2 = (k % 3) - 1;
        const float* cb = cell + b * 9;
        soff[threadIdx.x] = (float)f0 * cb[0 * 3 + d]
                          + (float)f1 * cb[1 * 3 + d]
                          + (float)f2 * cb[2 * 3 + d];
    }
    __syncthreads();

    const float pix = spos[i * 3 + 0];
    const float piy = spos[i * 3 + 1];
    const float piz = spos[i * 3 + 2];

    float* __restrict__ dist_out = out;
    float* __restrict__ vec_out  = out + S;
    float* __restrict__ mask_out = out + 4 * S;

    const int    NK   = N * KIMG;                 // 13824 = 9 * CH
    const size_t base = (size_t)bi * (size_t)NK;

    for (int c0 = 0; c0 < NK; c0 += CH) {
        // ---- compute phase: dist/mask direct (coalesced), vec -> smem ----
        #pragma unroll
        for (int q = 0; q < CH / TPB; q++) {
            const int lt = threadIdx.x + q * TPB;
            const int t  = c0 + lt;

            const int j = t / KIMG;
            const int k = t - j * KIMG;

            // vec = (pos_j + offset_k) - pos_i  (reference association order)
            const float vx = (spos[j * 3 + 0] + soff[k * 3 + 0]) - pix;
            const float vy = (spos[j * 3 + 1] + soff[k * 3 + 1]) - piy;
            const float vz = (spos[j * 3 + 2] + soff[k * 3 + 2]) - piz;

            const float sq = vx * vx + vy * vy + vz * vz;
            const bool  m  = (sq > 1e-8f) && (sq <= 25.0f);
            const float mf = m ? 1.0f : 0.0f;
            const float dd = m ? sqrtf(sq) : 0.0f;

            const size_t idx = base + (size_t)t;
            dist_out[idx] = dd;
            mask_out[idx] = mf;
            // conflict-free smem: bank = (3*lt + c) % 32, gcd(3,32)=1
            svec[lt * 3 + 0] = vx * mf;
            svec[lt * 3 + 1] = vy * mf;
            svec[lt * 3 + 2] = vz * mf;
        }
        __syncthreads();

        // ---- writeout phase: flat coalesced float4 stores of staged vec ----
        {
            float4* __restrict__ vdst = (float4*)(vec_out + (base + (size_t)c0) * 3);
            const float4* __restrict__ vsrc = (const float4*)svec;
            #pragma unroll
            for (int w = 0; w < (CH * 3 / 4) / TPB; w++) {   // 1152/256 -> iterates 4.5 -> handled below
                const int u4 = threadIdx.x + w * TPB;
                vdst[u4] = vsrc[u4];
            }
            // remainder (CH*3/4 = 1152 = 4*256 + 128)
            const int u4r = threadIdx.x + ((CH * 3 / 4) / TPB) * TPB;
            if (u4r < CH * 3 / 4)
                vdst[u4r] = vsrc[u4r];
        }
        __syncthreads();
    }

    // offset_cart tail: the i==0 block of each structure writes 81 floats
    if (i == 0 && threadIdx.x < KIMG * 3) {
        out[5 * S + (size_t)b * (KIMG * 3) + threadIdx.x] = soff[threadIdx.x];
    }
}

extern "C" void kernel_launch(void* const* d_in, const int* in_sizes, int n_in,
                              void* d_out, int out_size)
{
    const float* pos  = (const float*)d_in[0];  // [B, N, 3]
    const float* cell = (const float*)d_in[1];  // [B, 3, 3]

    const int B = in_sizes[1] / 9;              // 4
    const int N = in_sizes[0] / (3 * B);        // 512
    const size_t S = (size_t)B * N * N * KIMG;  // 28,311,552

    float* out = (float*)d_out;

    dim3 grid(B * N);
    dim3 block(TPB);
    radius_graph_kernel<<<grid, block>>>(pos, cell, out, B, N, S);
}